// round 12
// baseline (speedup 1.0000x reference)
#include <cuda_runtime.h>
#include <cuda_fp16.h>

typedef unsigned long long u64;
typedef unsigned int u32;
typedef __half fp16;

// ---------------- static device buffers (no allocation allowed) ----------------
// pixel-space level layout (each pixel = 256 ch): p3 [0,65536), p4 [65536,81920), p5 [81920,86016)
#define LVLPIX 86016ul
#define HALF   (LVLPIX * 256ul)        // elems per hi (or lo) plane across all levels
__device__ __align__(256) fp16 g_act0[2 * HALF];     // input feat planes [hi | lo]
__device__ __align__(256) fp16 g_c1[2 * HALF];       // cls ping
__device__ __align__(256) fp16 g_c2[2 * HALF];       // cls pong
__device__ __align__(256) fp16 g_x1[2 * HALF];       // box ping
__device__ __align__(256) fp16 g_x2[2 * HALF];       // box pong
__device__ __align__(256) fp16 g_wsh[8ul * 9 * 256 * 256];   // stem w: [branch*4+s][tap][co][ci]
__device__ __align__(256) fp16 g_wph[2ul * 9 * 128 * 256];   // pred w: [set][tap][co(128 pad)][ci]
__device__ float g_b5[8];                      // fused box(4)+ctr(1) bias

// ---------------- helpers ----------------
__device__ __forceinline__ u32 cvta_smem(const void* p) {
    u32 a;
    asm("{ .reg .u64 t; cvta.to.shared.u64 t, %1; cvt.u32.u64 %0, t; }" : "=r"(a) : "l"(p));
    return a;
}
__device__ __forceinline__ u32 sw64(u32 o) { return o ^ ((o >> 3) & 0x30); }

#define LDSM4(r0, r1, r2, r3, addr) \
    asm volatile("ldmatrix.sync.aligned.m8n8.x4.shared.b16 {%0,%1,%2,%3}, [%4];" \
        : "=r"(r0), "=r"(r1), "=r"(r2), "=r"(r3) : "r"(addr))

#define MMA16816(d, a, b0, b1) \
    asm volatile("mma.sync.aligned.m16n8k16.row.col.f32.f16.f16.f32 " \
        "{%0,%1,%2,%3}, {%4,%5,%6,%7}, {%8,%9}, {%0,%1,%2,%3};" \
        : "+f"((d)[0]), "+f"((d)[1]), "+f"((d)[2]), "+f"((d)[3]) \
        : "r"((a)[0]), "r"((a)[1]), "r"((a)[2]), "r"((a)[3]), "r"(b0), "r"(b1))

#define CPA_CG(d, s)     asm volatile("cp.async.cg.shared.global [%0], [%1], 16;" :: "r"(d), "l"(s))
#define CPA_CA(d, s, n)  asm volatile("cp.async.ca.shared.global [%0], [%1], 16, %2;" :: "r"(d), "l"(s), "r"(n))
#define CPA_COMMIT       asm volatile("cp.async.commit_group;" ::: "memory")
#define CPA_WAIT2        asm volatile("cp.async.wait_group 2;" ::: "memory")
#define CPA_WAIT0        asm volatile("cp.async.wait_group 0;" ::: "memory")

__device__ __forceinline__ void fp16_split(float x, fp16& h, fp16& l) {
    h = __float2half_rn(x);
    l = __float2half_rn(x - __half2float(h));
}

// ---------------- prepass: fp32 NCHW -> NHWC fp16 hi/lo planes ----------------
__global__ void to_planes(const float* __restrict__ in, fp16* __restrict__ hi,
                          int logHW, u32 pixBase) {
    __shared__ float t[32][33];
    const int HW = 1 << logHW;
    int hw0 = blockIdx.x * 32, c0 = blockIdx.y * 32, b = blockIdx.z;
    int tx = threadIdx.x, ty = threadIdx.y;
    const float* ib = in + ((size_t)b * 256 + c0) * HW + hw0;
#pragma unroll
    for (int i = 0; i < 4; i++) t[ty + i * 8][tx] = ib[(size_t)(ty + i * 8) * HW + tx];
    __syncthreads();
#pragma unroll
    for (int i = 0; i < 4; i++) {
        int yy = ty + i * 8;
        float v = t[tx][yy];
        size_t o = (((size_t)pixBase + ((size_t)b << logHW) + hw0 + yy) << 8) + c0 + tx;
        fp16 h, l; fp16_split(v, h, l);
        hi[o] = h; hi[HALF + o] = l;
    }
}

// ---------------- prepass: stem weights -> per-tap fp16 planes ----------------
__global__ void conv_stem_w(const float* __restrict__ w, fp16* __restrict__ dh) {
    int idx = blockIdx.x * 256 + threadIdx.x;   // layout: ((s*9+tap)<<16)|(co<<8)|ci
    int ci  = idx & 255;
    int co  = (idx >> 8) & 255;
    int st  = idx >> 16;
    int s = st / 9, tap = st % 9;
    dh[idx] = __float2half_rn(w[(((size_t)s * 256 + co) * 256 + ci) * 9 + tap]);
}

// ---------------- prepass: pred weights (padded to 128 rows) ----------------
__global__ void conv_pred_w(const float* __restrict__ wA, int nA, const float* __restrict__ wB,
                            fp16* __restrict__ dh) {
    int idx = blockIdx.x * 256 + threadIdx.x;   // layout: (tap<<15)|(co<<8)|ci
    int ci  = idx & 255;
    int co  = (idx >> 8) & 127;
    int tap = idx >> 15;
    float v = 0.f;
    if (co < nA)               v = wA[((size_t)co * 256 + ci) * 9 + tap];
    else if (wB && co == nA)   v = wB[(size_t)ci * 9 + tap];
    dh[idx] = __float2half_rn(v);
}

__global__ void pack_b5(const float* bb, const float* bc) {
    int i = threadIdx.x;
    if (i < 4) g_b5[i] = bb[i];
    else if (i == 4) g_b5[4] = bc[0];
}

// ---------------- main conv: 4-stage cp.async fp16 2-product GEMM -------------
// ALL levels in one launch: blockIdx.x 0..31 = p3 tiles, 32..39 = p4, 40..41 = p5.
// Branch-merged: blockIdx.z = b + 16*branch. Chunks tap-fastest (tap=k%9).
// MODE 0: stem (bias+ReLU -> fp16 hi/lo planes, coalesced via smem transpose)
// MODE 1: pred (bias -> fp32 (B,5376,85); set 0 = cls(80), set 1 = box+ctr(5))
#define STAGE 24576
#define NSTG  4
#define SMEMSZ (NSTG * STAGE)
template <int MODE>
__global__ __launch_bounds__(256, 2)
void conv_mma(const fp16* __restrict__ w0, const fp16* __restrict__ w1, int wM,
              const fp16* __restrict__ x0, const fp16* __restrict__ x1,
              const float* __restrict__ bias0, const float* __restrict__ bias1,
              fp16* __restrict__ o0, fp16* __restrict__ o1,
              float* __restrict__ opred, int biasStride)
{
    extern __shared__ __align__(1024) char smem[];
    const u32 sb = cvta_smem(smem);
    const int tid  = threadIdx.x;
    const int wid  = tid >> 5, lane = tid & 31;
    const int mw   = wid & 1;          // 0/1 : co block of 64
    const int nw   = wid >> 1;         // 0..3: px block of 32
    const int br   = blockIdx.z >> 4;  // branch/set
    const int b    = blockIdx.z & 15;
    const int co_base = blockIdx.y * 128;

    // ---- level decode from blockIdx.x
    int bx = blockIdx.x;
    int logW, logHW, row_off; u32 pixBase; int tile;
    if (bx < 32)      { tile = bx;      logW = 6; logHW = 12; row_off = 0;    pixBase = 0; }
    else if (bx < 40) { tile = bx - 32; logW = 5; logHW = 10; row_off = 4096; pixBase = 65536; }
    else              { tile = bx - 40; logW = 4; logHW = 8;  row_off = 5120; pixBase = 81920; }
    const int P0 = tile * 128;
    const int Wd = 1 << logW;
    const int Hh = 1 << (logHW - logW);

    const fp16* xh = br ? x1 : x0;     // hi plane; lo = +HALF
    const fp16* wh = br ? w1 : w0;

    float acc[4][4][4];
#pragma unroll
    for (int i = 0; i < 4; i++)
#pragma unroll
        for (int j = 0; j < 4; j++)
#pragma unroll
            for (int e = 0; e < 4; e++) acc[i][j][e] = 0.f;

    // ldmatrix lane addressing (within 64B-row tiles)
    const u32 aRow = mw * 64 + (lane & 15);
    const u32 aCol = (lane >> 4) << 4;
    const u32 bRow = nw * 32 + (lane & 7) + ((lane >> 4) & 1) * 8;
    const u32 bCol = ((lane >> 3) & 1) << 4;

    // ---- chunk staging via cp.async (all 256 threads; 6 cp.async each) ----
    auto stage_chunk = [&](int k, u32 bufoff) {
        int ci_i = k / 9;
        int tap  = k - ci_i * 9;       // tap-fastest
        int ci0  = ci_i << 5;
        int dy = tap / 3 - 1, dx = tap % 3 - 1;
        // A (weights fp16): 128 rows x 64B
#pragma unroll
        for (int i = 0; i < 2; i++) {
            int idx = tid + (i << 8);
            int r   = idx >> 2;
            int s   = idx & 3;
            const fp16* src = wh + (((size_t)(tap * wM + co_base + r)) << 8) + ci0 + (s << 3);
            u32 dst = sb + bufoff + sw64((r << 6) | (s << 4));
            CPA_CG(dst, src);
        }
        // B (activations) hi/lo: 2 planes x 128 px x 64B, zero-filled at borders
#pragma unroll
        for (int i = 0; i < 4; i++) {
            int idx = tid + (i << 8);
            int lof = idx >> 9;
            int r   = (idx >> 2) & 127;
            int s   = idx & 3;
            int p   = P0 + r;
            int y = p >> logW, x = p & (Wd - 1);
            int sy = y + dy, sx = x + dx;
            u32 ok = ((unsigned)sy < (unsigned)Hh && (unsigned)sx < (unsigned)Wd) ? 16u : 0u;
            int csy = ok ? sy : 0, csx = ok ? sx : 0;
            const fp16* src = xh + (size_t)lof * HALF
                + ((((size_t)pixBase + ((size_t)b << logHW) + ((size_t)csy << logW) + csx)) << 8)
                + ci0 + (s << 3);
            u32 dst = sb + bufoff + 8192u + ((u32)lof << 13) + sw64((r << 6) | (s << 4));
            CPA_CA(dst, src, ok);
        }
    };

    stage_chunk(0, 0); CPA_COMMIT;
    stage_chunk(1, STAGE); CPA_COMMIT;
    stage_chunk(2, 2 * STAGE); CPA_COMMIT;

    for (int k = 0; k < 72; k++) {
        u32 cur = (u32)(k & 3) * STAGE;
        if (k < 70) CPA_WAIT2; else CPA_WAIT0;
        __syncthreads();   // chunk k visible to all; all warps done consuming k-1
        if (k < 69) { stage_chunk(k + 3, (u32)((k + 3) & 3) * STAGE); CPA_COMMIT; }

        const u32 Ah = sb + cur;
        const u32 Bh = Ah + 8192u, Bl = Ah + 16384u;
#pragma unroll
        for (int k16 = 0; k16 < 2; k16++) {
            const u32 kb = (u32)k16 << 5;
            u32 ah[4][4], bh[2][4], bl[2][4];
#pragma unroll
            for (int i = 0; i < 4; i++)
                LDSM4(ah[i][0], ah[i][1], ah[i][2], ah[i][3],
                      Ah + sw64(((aRow + i * 16) << 6) + kb + aCol));
#pragma unroll
            for (int g = 0; g < 2; g++)
                LDSM4(bh[g][0], bh[g][1], bh[g][2], bh[g][3],
                      Bh + sw64(((bRow + g * 16) << 6) + kb + bCol));
#pragma unroll
            for (int g = 0; g < 2; g++)
                LDSM4(bl[g][0], bl[g][1], bl[g][2], bl[g][3],
                      Bl + sw64(((bRow + g * 16) << 6) + kb + bCol));
#pragma unroll
            for (int i = 0; i < 4; i++)
#pragma unroll
                for (int j = 0; j < 4; j++) {
                    MMA16816(acc[i][j], ah[i], bh[j >> 1][2 * (j & 1)], bh[j >> 1][2 * (j & 1) + 1]);
                    MMA16816(acc[i][j], ah[i], bl[j >> 1][2 * (j & 1)], bl[j >> 1][2 * (j & 1) + 1]);
                }
        }
    }

    if (MODE == 0) {
        // ---- coalesced epilogue: acc -> smem [px][ch] (swizzled) -> uint4 STG
        fp16* oh = br ? o1 : o0;
        const float* bias = br ? bias1 : bias0;
        __syncthreads();   // mainloop smem ring now free
#pragma unroll
        for (int i = 0; i < 4; i++) {
            int cl0 = mw * 64 + i * 16 + (lane >> 2);
            float bv0 = bias[co_base + cl0];
            float bv1 = bias[co_base + cl0 + 8];
#pragma unroll
            for (int j = 0; j < 4; j++) {
                int pxb = nw * 32 + j * 8 + ((lane & 3) << 1);
#pragma unroll
                for (int e = 0; e < 4; e++) {
                    int cl = (e < 2) ? cl0 : cl0 + 8;
                    float bv = (e < 2) ? bv0 : bv1;
                    int px = pxb + (e & 1);
                    float xv = fmaxf(acc[i][j][e] + bv, 0.f);
                    fp16 h, l; fp16_split(xv, h, l);
                    u32 off = (u32)px * 256 + (((u32)cl * 2) ^ (((u32)px & 15) << 4));
                    *(fp16*)(smem + off) = h;
                    *(fp16*)(smem + 32768 + off) = l;
                }
            }
        }
        __syncthreads();
#pragma unroll
        for (int ii = 0; ii < 16; ii++) {
            int idx = tid + (ii << 8);
            int plane = idx >> 11;
            int rem = idx & 2047;
            int px  = rem >> 4;
            int seg = rem & 15;
            u32 soff = (u32)plane * 32768 + (u32)px * 256 + (((u32)seg * 16) ^ (((u32)px & 15) << 4));
            uint4 v = *(uint4*)(smem + soff);
            fp16* dst = oh + (size_t)plane * HALF
                + (((size_t)pixBase + ((size_t)b << logHW) + P0 + px) << 8) + co_base + seg * 8;
            *(uint4*)dst = v;
        }
    } else {
        // ---- pred epilogue: scalar fp32 into (B,5376,85)
        const float* bias = br ? bias1 : bias0;
        const int co_off = br ? 80 : 0;
        const int coutA  = br ? 5 : 80;
#pragma unroll
        for (int i = 0; i < 4; i++) {
            int cl0 = mw * 64 + i * 16 + (lane >> 2);
            int cl1 = cl0 + 8;
            float bv0 = (cl0 < coutA) ? bias[cl0] : 0.f;
            float bv1 = (cl1 < coutA) ? bias[cl1] : 0.f;
#pragma unroll
            for (int j = 0; j < 4; j++) {
                int px = P0 + nw * 32 + j * 8 + ((lane & 3) << 1);
#pragma unroll
                for (int e = 0; e < 4; e++) {
                    int cl = (e < 2) ? cl0 : cl1;
                    float bv = (e < 2) ? bv0 : bv1;
                    int p = px + (e & 1);
                    if (cl < coutA)
                        opred[((size_t)b * 5376 + row_off + p) * 85 + co_off + cl] = acc[i][j][e] + bv;
                }
            }
        }
    }
}

// ---------------- host launcher ----------------
extern "C" void kernel_launch(void* const* d_in, const int* in_sizes, int n_in,
                              void* d_out, int out_size)
{
    const float* f[13];
    for (int i = 0; i < 13; i++) f[i] = (const float*)d_in[i];
    float* out = (float*)d_out;

    fp16 *a0, *c1, *c2, *x1, *x2, *wsh, *wph;
    float* b5;
    cudaGetSymbolAddress((void**)&a0, g_act0);
    cudaGetSymbolAddress((void**)&c1, g_c1);
    cudaGetSymbolAddress((void**)&c2, g_c2);
    cudaGetSymbolAddress((void**)&x1, g_x1);
    cudaGetSymbolAddress((void**)&x2, g_x2);
    cudaGetSymbolAddress((void**)&wsh, g_wsh);
    cudaGetSymbolAddress((void**)&wph, g_wph);
    cudaGetSymbolAddress((void**)&b5, g_b5);

    cudaFuncSetAttribute(conv_mma<0>, cudaFuncAttributeMaxDynamicSharedMemorySize, SMEMSZ);
    cudaFuncSetAttribute(conv_mma<1>, cudaFuncAttributeMaxDynamicSharedMemorySize, SMEMSZ);

    // weight/bias prepasses
    pack_b5<<<1, 8>>>(f[10], f[12]);
    conv_stem_w<<<9216, 256>>>(f[3], wsh);                       // cls stems
    conv_stem_w<<<9216, 256>>>(f[5], wsh + 36ul * 65536);        // box stems
    conv_pred_w<<<1152, 256>>>(f[7], 80, nullptr, wph);          // cls pred
    conv_pred_w<<<1152, 256>>>(f[9], 4, f[11], wph + 9ul * 32768); // box+ctr

    // input planes for all three levels
    to_planes<<<dim3(128, 8, 16), dim3(32, 8)>>>(f[0], a0, 12, 0);
    to_planes<<<dim3(32, 8, 16),  dim3(32, 8)>>>(f[1], a0, 10, 65536);
    to_planes<<<dim3(8, 8, 16),   dim3(32, 8)>>>(f[2], a0, 8, 81920);

    // merged-level stem layers (42 x-tiles cover p3+p4+p5)
    dim3 gs(42, 2, 32), gp(42, 1, 32);
    const size_t WL = 9ul * 65536;   // one stem layer's weight plane
    conv_mma<0><<<gs, 256, SMEMSZ>>>(wsh + 0 * WL, wsh + 36ul * 65536 + 0 * WL, 256,
        a0, a0, f[4] + 0, f[6] + 0, c1, x1, nullptr, 256);
    conv_mma<0><<<gs, 256, SMEMSZ>>>(wsh + 1 * WL, wsh + 36ul * 65536 + 1 * WL, 256,
        c1, x1, f[4] + 256, f[6] + 256, c2, x2, nullptr, 256);
    conv_mma<0><<<gs, 256, SMEMSZ>>>(wsh + 2 * WL, wsh + 36ul * 65536 + 2 * WL, 256,
        c2, x2, f[4] + 512, f[6] + 512, c1, x1, nullptr, 256);
    conv_mma<0><<<gs, 256, SMEMSZ>>>(wsh + 3 * WL, wsh + 36ul * 65536 + 3 * WL, 256,
        c1, x1, f[4] + 768, f[6] + 768, c2, x2, nullptr, 256);
    // pred: set 0 = cls from c2, set 1 = box+ctr from x2
    conv_mma<1><<<gp, 256, SMEMSZ>>>(wph, wph + 9ul * 32768, 128,
        c2, x2, f[8], b5, nullptr, nullptr, out, 0);
}

// round 16
// speedup vs baseline: 1.4544x; 1.4544x over previous
#include <cuda_runtime.h>
#include <cuda_fp16.h>

typedef unsigned long long u64;
typedef unsigned int u32;
typedef __half fp16;

#define PLANE (16ul * 4096 * 256)
__device__ __align__(256) fp16 g_act0[2 * PLANE];
__device__ __align__(256) fp16 g_c1[2 * PLANE];
__device__ __align__(256) fp16 g_c2[2 * PLANE];
__device__ __align__(256) fp16 g_x1[2 * PLANE];
__device__ __align__(256) fp16 g_x2[2 * PLANE];
__device__ __align__(256) fp16 g_wsh[8ul * 9 * 256 * 256];
__device__ __align__(256) fp16 g_wph[2ul * 9 * 128 * 256];
__device__ float g_b5[8];

__device__ __forceinline__ u32 cvta_smem(const void* p) {
    u32 a;
    asm("{ .reg .u64 t; cvta.to.shared.u64 t, %1; cvt.u32.u64 %0, t; }" : "=r"(a) : "l"(p));
    return a;
}
__device__ __forceinline__ u32 sw64(u32 o) { return o ^ ((o >> 3) & 0x30); }

#define LDSM4(r0, r1, r2, r3, addr) \
    asm volatile("ldmatrix.sync.aligned.m8n8.x4.shared.b16 {%0,%1,%2,%3}, [%4];" \
        : "=r"(r0), "=r"(r1), "=r"(r2), "=r"(r3) : "r"(addr))

#define MMA16816(d, a, b0, b1) \
    asm volatile("mma.sync.aligned.m16n8k16.row.col.f32.f16.f16.f32 " \
        "{%0,%1,%2,%3}, {%4,%5,%6,%7}, {%8,%9}, {%0,%1,%2,%3};" \
        : "+f"((d)[0]), "+f"((d)[1]), "+f"((d)[2]), "+f"((d)[3]) \
        : "r"((a)[0]), "r"((a)[1]), "r"((a)[2]), "r"((a)[3]), "r"(b0), "r"(b1))

#define CPA_CG(d, s)     asm volatile("cp.async.cg.shared.global [%0], [%1], 16;" :: "r"(d), "l"(s))
#define CPA_CA(d, s, n)  asm volatile("cp.async.ca.shared.global [%0], [%1], 16, %2;" :: "r"(d), "l"(s), "r"(n))
#define CPA_COMMIT       asm volatile("cp.async.commit_group;" ::: "memory")
#define CPA_WAIT1        asm volatile("cp.async.wait_group 1;" ::: "memory")
#define CPA_WAIT0        asm volatile("cp.async.wait_group 0;" ::: "memory")

__device__ __forceinline__ void fp16_split(float x, fp16& h, fp16& l) {
    h = __float2half_rn(x);
    l = __float2half_rn(x - __half2float(h));
}

// ---------------- merged prepass: all weights + fused bias --------------------
__global__ void prep_weights(const float* __restrict__ wc, const float* __restrict__ wb,
                             const float* __restrict__ wpc, const float* __restrict__ wpb,
                             const float* __restrict__ wpt,
                             const float* __restrict__ bb, const float* __restrict__ bc,
                             fp16* __restrict__ dsh, fp16* __restrict__ dph) {
    int bx = blockIdx.x;
    if (bx < 18432) {
        int half = bx >= 9216;
        int idx = (bx - half * 9216) * 256 + threadIdx.x;
        int ci  = idx & 255;
        int co  = (idx >> 8) & 255;
        int st  = idx >> 16;
        int s = st / 9, tap = st % 9;
        const float* w = half ? wb : wc;
        dsh[(size_t)half * 36 * 65536 + idx] =
            __float2half_rn(w[(((size_t)s * 256 + co) * 256 + ci) * 9 + tap]);
    } else if (bx < 20736) {
        int half = bx >= 19584;
        int idx = (bx - 18432 - half * 1152) * 256 + threadIdx.x;
        int ci  = idx & 255;
        int co  = (idx >> 8) & 127;
        int tap = idx >> 15;
        float v = 0.f;
        if (!half) {
            if (co < 80) v = wpc[((size_t)co * 256 + ci) * 9 + tap];
        } else {
            if (co < 4)       v = wpb[((size_t)co * 256 + ci) * 9 + tap];
            else if (co == 4) v = wpt[(size_t)ci * 9 + tap];
        }
        dph[(size_t)half * 9 * 32768 + idx] = __float2half_rn(v);
    } else {
        int i = threadIdx.x;
        if (i < 4) g_b5[i] = bb[i];
        else if (i == 4) g_b5[4] = bc[0];
    }
}

// ---------------- prepass: fp32 NCHW -> NHWC fp16 hi/lo planes ----------------
__global__ void to_planes(const float* __restrict__ in, fp16* __restrict__ hi,
                          fp16* __restrict__ lo, int logHW) {
    __shared__ float t[32][33];
    const int HW = 1 << logHW;
    int hw0 = blockIdx.x * 32, c0 = blockIdx.y * 32, b = blockIdx.z;
    int tx = threadIdx.x, ty = threadIdx.y;
    const float* ib = in + ((size_t)b * 256 + c0) * HW + hw0;
#pragma unroll
    for (int i = 0; i < 4; i++) t[ty + i * 8][tx] = ib[(size_t)(ty + i * 8) * HW + tx];
    __syncthreads();
#pragma unroll
    for (int i = 0; i < 4; i++) {
        int yy = ty + i * 8;
        float v = t[tx][yy];
        size_t o = ((((size_t)b << logHW) + hw0 + yy) << 8) + c0 + tx;
        fp16 h, l; fp16_split(v, h, l);
        hi[o] = h; lo[o] = l;
    }
}

// ---------------- main conv: 3-stage cp.async fp16 2-product GEMM -------------
#define STAGE 24576
#define SMEMSZ (3 * STAGE)
template <int MODE>
__global__ __launch_bounds__(256, 2)
void conv_mma(const fp16* __restrict__ w0, const fp16* __restrict__ w1, int wM,
              const fp16* __restrict__ x0h, const fp16* __restrict__ x0l,
              const fp16* __restrict__ x1h, const fp16* __restrict__ x1l,
              const float* __restrict__ bias0, const float* __restrict__ bias1,
              fp16* __restrict__ o0h, fp16* __restrict__ o0l,
              fp16* __restrict__ o1h, fp16* __restrict__ o1l,
              float* __restrict__ opred,
              int logW, int logHW, int row_off)
{
    extern __shared__ __align__(1024) char smem[];
    const u32 sb = cvta_smem(smem);
    const int tid  = threadIdx.x;
    const int wid  = tid >> 5, lane = tid & 31;
    const int mw   = wid & 1;
    const int nw   = wid >> 1;
    const int br   = blockIdx.z >> 4;
    const int b    = blockIdx.z & 15;
    const int P0   = blockIdx.x * 128;
    const int co_base = blockIdx.y * 128;
    const int Wd = 1 << logW;
    const int Hh = 1 << (logHW - logW);

    const fp16* wh  = br ? w1 : w0;
    const fp16* xhi = br ? x1h : x0h;
    const fp16* xlo = br ? x1l : x0l;

    float acc[4][4][4];
#pragma unroll
    for (int i = 0; i < 4; i++)
#pragma unroll
        for (int j = 0; j < 4; j++)
#pragma unroll
            for (int e = 0; e < 4; e++) acc[i][j][e] = 0.f;

    const u32 aRow = mw * 64 + (lane & 15);
    const u32 aCol = (lane >> 4) << 4;
    const u32 bRow = nw * 32 + (lane & 7) + ((lane >> 4) & 1) * 8;
    const u32 bCol = ((lane >> 3) & 1) << 4;

    auto stage_chunk = [&](int k, u32 bufoff) {
        int ci_i = k / 9;
        int tap  = k - ci_i * 9;
        int ci0  = ci_i << 5;
        int dy = tap / 3 - 1, dx = tap % 3 - 1;
#pragma unroll
        for (int i = 0; i < 2; i++) {
            int idx = tid + (i << 8);
            int r   = idx >> 2;
            int s   = idx & 3;
            const fp16* src = wh + (((size_t)(tap * wM + co_base + r)) << 8) + ci0 + (s << 3);
            u32 dst = sb + bufoff + sw64((r << 6) | (s << 4));
            CPA_CG(dst, src);
        }
#pragma unroll
        for (int i = 0; i < 4; i++) {
            int idx = tid + (i << 8);
            int lof = idx >> 9;
            int r   = (idx >> 2) & 127;
            int s   = idx & 3;
            int p   = P0 + r;
            int y = p >> logW, x = p & (Wd - 1);
            int sy = y + dy, sx = x + dx;
            u32 ok = ((unsigned)sy < (unsigned)Hh && (unsigned)sx < (unsigned)Wd) ? 16u : 0u;
            int csy = ok ? sy : 0, csx = ok ? sx : 0;
            const fp16* src = (lof ? xlo : xhi)
                + (((((size_t)b << logHW) + ((size_t)csy << logW) + csx)) << 8) + ci0 + (s << 3);
            u32 dst = sb + bufoff + 8192u + ((u32)lof << 13) + sw64((r << 6) | (s << 4));
            CPA_CA(dst, src, ok);
        }
    };

    stage_chunk(0, 0); CPA_COMMIT;
    stage_chunk(1, STAGE); CPA_COMMIT;

    for (int k = 0; k < 72; k++) {
        u32 cur = (u32)(k % 3) * STAGE;
        if (k < 71) CPA_WAIT1; else CPA_WAIT0;
        __syncthreads();
        if (k < 70) { stage_chunk(k + 2, (u32)((k + 2) % 3) * STAGE); CPA_COMMIT; }

        const u32 Ah = sb + cur;
        const u32 Bh = Ah + 8192u, Bl = Ah + 16384u;
#pragma unroll
        for (int k16 = 0; k16 < 2; k16++) {
            const u32 kb = (u32)k16 << 5;
            u32 ah[4][4], bh[2][4], bl[2][4];
#pragma unroll
            for (int i = 0; i < 4; i++)
                LDSM4(ah[i][0], ah[i][1], ah[i][2], ah[i][3],
                      Ah + sw64(((aRow + i * 16) << 6) + kb + aCol));
#pragma unroll
            for (int g = 0; g < 2; g++)
                LDSM4(bh[g][0], bh[g][1], bh[g][2], bh[g][3],
                      Bh + sw64(((bRow + g * 16) << 6) + kb + bCol));
#pragma unroll
            for (int g = 0; g < 2; g++)
                LDSM4(bl[g][0], bl[g][1], bl[g][2], bl[g][3],
                      Bl + sw64(((bRow + g * 16) << 6) + kb + bCol));
#pragma unroll
            for (int i = 0; i < 4; i++)
#pragma unroll
                for (int j = 0; j < 4; j++) {
                    MMA16816(acc[i][j], ah[i], bh[j >> 1][2 * (j & 1)], bh[j >> 1][2 * (j & 1) + 1]);
                    MMA16816(acc[i][j], ah[i], bl[j >> 1][2 * (j & 1)], bl[j >> 1][2 * (j & 1) + 1]);
                }
        }
    }

    if (MODE == 0) {
        fp16* ohi = br ? o1h : o0h;
        fp16* olo = br ? o1l : o0l;
        const float* bias = br ? bias1 : bias0;
        __syncthreads();
#pragma unroll
        for (int i = 0; i < 4; i++) {
            int cl0 = mw * 64 + i * 16 + (lane >> 2);
            float bv0 = bias[co_base + cl0];
            float bv1 = bias[co_base + cl0 + 8];
#pragma unroll
            for (int j = 0; j < 4; j++) {
                int pxb = nw * 32 + j * 8 + ((lane & 3) << 1);
#pragma unroll
                for (int e = 0; e < 4; e++) {
                    int cl = (e < 2) ? cl0 : cl0 + 8;
                    float bv = (e < 2) ? bv0 : bv1;
                    int px = pxb + (e & 1);
                    float xv = fmaxf(acc[i][j][e] + bv, 0.f);
                    fp16 h, l; fp16_split(xv, h, l);
                    u32 off = (u32)px * 256 + (((u32)cl * 2) ^ (((u32)px & 15) << 4));
                    *(fp16*)(smem + off) = h;
                    *(fp16*)(smem + 32768 + off) = l;
                }
            }
        }
        __syncthreads();
#pragma unroll
        for (int ii = 0; ii < 16; ii++) {
            int idx = tid + (ii << 8);
            int plane = idx >> 11;
            int rem = idx & 2047;
            int px  = rem >> 4;
            int seg = rem & 15;
            u32 soff = (u32)plane * 32768 + (u32)px * 256 + (((u32)seg * 16) ^ (((u32)px & 15) << 4));
            uint4 v = *(uint4*)(smem + soff);
            fp16* dst = (plane ? olo : ohi)
                + ((((size_t)b << logHW) + P0 + px) << 8) + co_base + seg * 8;
            *(uint4*)dst = v;
        }
    } else {
        const float* bias = br ? bias1 : bias0;
        const int co_off = br ? 80 : 0;
        const int coutA  = br ? 5 : 80;
#pragma unroll
        for (int i = 0; i < 4; i++) {
            int cl0 = mw * 64 + i * 16 + (lane >> 2);
            int cl1 = cl0 + 8;
            float bv0 = (cl0 < coutA) ? bias[cl0] : 0.f;
            float bv1 = (cl1 < coutA) ? bias[cl1] : 0.f;
#pragma unroll
            for (int j = 0; j < 4; j++) {
                int px = P0 + nw * 32 + j * 8 + ((lane & 3) << 1);
#pragma unroll
                for (int e = 0; e < 4; e++) {
                    int cl = (e < 2) ? cl0 : cl1;
                    float bv = (e < 2) ? bv0 : bv1;
                    int p = px + (e & 1);
                    if (cl < coutA)
                        opred[((size_t)b * 5376 + row_off + p) * 85 + co_off + cl] = acc[i][j][e] + bv;
                }
            }
        }
    }
}

// ---------------- host launcher ----------------
extern "C" void kernel_launch(void* const* d_in, const int* in_sizes, int n_in,
                              void* d_out, int out_size)
{
    const float* f[13];
    for (int i = 0; i < 13; i++) f[i] = (const float*)d_in[i];
    float* out = (float*)d_out;

    fp16 *a0, *c1, *c2, *x1, *x2, *wsh, *wph;
    float* b5;
    cudaGetSymbolAddress((void**)&a0, g_act0);
    cudaGetSymbolAddress((void**)&c1, g_c1);
    cudaGetSymbolAddress((void**)&c2, g_c2);
    cudaGetSymbolAddress((void**)&x1, g_x1);
    cudaGetSymbolAddress((void**)&x2, g_x2);
    cudaGetSymbolAddress((void**)&wsh, g_wsh);
    cudaGetSymbolAddress((void**)&wph, g_wph);
    cudaGetSymbolAddress((void**)&b5, g_b5);

    cudaFuncSetAttribute(conv_mma<0>, cudaFuncAttributeMaxDynamicSharedMemorySize, SMEMSZ);
    cudaFuncSetAttribute(conv_mma<1>, cudaFuncAttributeMaxDynamicSharedMemorySize, SMEMSZ);

    // single merged weight prepass
    prep_weights<<<20737, 256>>>(f[3], f[5], f[7], f[9], f[11], f[10], f[12], wsh, wph);

    struct Lv { const float* feat; int logW, logHW, row_off; };
    const Lv lv[3] = { { f[0], 6, 12, 0 }, { f[1], 5, 10, 4096 }, { f[2], 4, 8, 5120 } };
    const size_t WL = 9ul * 65536;

    for (int l = 0; l < 3; l++) {
        const int logW = lv[l].logW, logHW = lv[l].logHW, row_off = lv[l].row_off;
        const int HW = 1 << logHW;
        to_planes<<<dim3(HW / 32, 8, 16), dim3(32, 8)>>>(lv[l].feat, a0, a0 + PLANE, logHW);

        dim3 gs(HW / 128, 2, 32), gp(HW / 128, 1, 32);
        conv_mma<0><<<gs, 256, SMEMSZ>>>(wsh + 0 * WL, wsh + 36ul * 65536 + 0 * WL, 256,
            a0, a0 + PLANE, a0, a0 + PLANE, f[4] + 0, f[6] + 0,
            c1, c1 + PLANE, x1, x1 + PLANE, nullptr, logW, logHW, 0);
        conv_mma<0><<<gs, 256, SMEMSZ>>>(wsh + 1 * WL, wsh + 36ul * 65536 + 1 * WL, 256,
            c1, c1 + PLANE, x1, x1 + PLANE, f[4] + 256, f[6] + 256,
            c2, c2 + PLANE, x2, x2 + PLANE, nullptr, logW, logHW, 0);
        conv_mma<0><<<gs, 256, SMEMSZ>>>(wsh + 2 * WL, wsh + 36ul * 65536 + 2 * WL, 256,
            c2, c2 + PLANE, x2, x2 + PLANE, f[4] + 512, f[6] + 512,
            c1, c1 + PLANE, x1, x1 + PLANE, nullptr, logW, logHW, 0);
        conv_mma<0><<<gs, 256, SMEMSZ>>>(wsh + 3 * WL, wsh + 36ul * 65536 + 3 * WL, 256,
            c1, c1 + PLANE, x1, x1 + PLANE, f[4] + 768, f[6] + 768,
            c2, c2 + PLANE, x2, x2 + PLANE, nullptr, logW, logHW, 0);
        conv_mma<1><<<gp, 256, SMEMSZ>>>(wph, wph + 9ul * 32768, 128,
            c2, c2 + PLANE, x2, x2 + PLANE, f[8], b5,
            nullptr, nullptr, nullptr, nullptr, out, logW, logHW, row_off);
    }
}